// round 16
// baseline (speedup 1.0000x reference)
#include <cuda_runtime.h>
#include <cstdint>

#define G    8
#define CG   32
#define CH   256
#define HWP  16384
#define TPB  256
#define PT   64
#define NT   4096

typedef unsigned long long ull;

__device__ __forceinline__ ull pack2(float a, float b) {
    ull r; asm("mov.b64 %0, {%1,%2};" : "=l"(r) : "f"(a), "f"(b)); return r;
}
__device__ __forceinline__ void unpack2(ull v, float& a, float& b) {
    asm("mov.b64 {%0,%1}, %2;" : "=f"(a), "=f"(b) : "l"(v));
}
__device__ __forceinline__ void fma2(ull& d, ull a, ull b) {   // d += a*b (packed)
    asm("fma.rn.f32x2 %0, %1, %2, %0;" : "+l"(d) : "l"(a), "l"(b));
}
__device__ __forceinline__ ull add2(ull a, ull b) {
    ull r; asm("add.rn.f32x2 %0, %1, %2;" : "=l"(r) : "l"(a), "l"(b)); return r;
}
__device__ __forceinline__ ull mul2(ull a, ull b) {
    ull r; asm("mul.rn.f32x2 %0, %1, %2;" : "=l"(r) : "l"(a), "l"(b)); return r;
}

// sort 4 floats descending: a>=b>=c>=d (10 ops, scalar — no packed min/max in PTX)
__device__ __forceinline__ void sort4(float w, float x, float y, float z,
                                      float& a, float& b, float& c, float& d) {
    float h1 = fmaxf(w, x), l1 = fminf(w, x);
    float h2 = fmaxf(y, z), l2 = fminf(y, z);
    a = fmaxf(h1, h2); float t = fminf(h1, h2);
    d = fminf(l1, l2); float u = fmaxf(l1, l2);
    b = fmaxf(t, u);  c = fminf(t, u);
}

// top4(A ∪ P), both sorted descending (12 ops; bitonic cleanup — validated R10-R14)
__device__ __forceinline__ void merge4(float& a, float& b, float& c, float& d,
                                       float p, float q, float r, float s) {
    float m1 = fmaxf(a, s), m2 = fmaxf(b, r);
    float m3 = fmaxf(c, q), m4 = fmaxf(d, p);
    float r1 = fmaxf(m1, m3), r3 = fminf(m1, m3);
    float r2 = fmaxf(m2, m4), r4 = fminf(m2, m4);
    a = fmaxf(r1, r2); b = fminf(r1, r2);
    c = fmaxf(r3, r4); d = fminf(r3, r4);
}

__global__ void __launch_bounds__(TPB, 3)
cgblock_kernel(const float* __restrict__ x,
               const float* __restrict__ soft_w1,
               const float* __restrict__ soft_w2,
               const float* __restrict__ top_w1,
               const float* __restrict__ top_w2,
               const float* __restrict__ rr,
               float* __restrict__ out)
{
    __shared__ __align__(16) ull s_w2[CH * 8];      // (ws,wt) per (o,g): 16KB
    __shared__ __align__(16) ull s_st[2][G][PT];    // stats (sv,tv): [buf][g][px], 8KB
    __shared__ __align__(16) ull s_w1p[G * CG];     // (w,w) dup pairs: 2KB
    __shared__ float s_tw1[G * 4];

    const int tid  = threadIdx.x;
    const int warp = tid >> 5;
    const int lane = tid & 31;

    // ---- one-time weight prep ----
    {
        float r0 = __ldg(rr), r1 = __ldg(rr + 1);
        float rm = fmaxf(r0, r1);
        float e0 = __expf(r0 - rm), e1 = __expf(r1 - rm);
        float inv = __frcp_rn(e0 + e1);
        float w_top = e0 * inv, w_soft = e1 * inv;
        #pragma unroll
        for (int i = tid; i < CH * G; i += TPB) {
            int o = i >> 3, g = i & 7;
            s_w2[i] = pack2(w_soft * __ldg(soft_w2 + o * G + g),
                            w_top  * __ldg(top_w2  + o * G + g));
        }
        #pragma unroll
        for (int i = tid; i < G * CG; i += TPB) {
            float w = __ldg(soft_w1 + i);
            s_w1p[i] = pack2(w, w);
        }
        if (tid < G * 4) s_tw1[tid] = __ldg(top_w1 + tid);
    }
    __syncthreads();

    const int S = gridDim.x;
    int it = 0;
    for (int t = blockIdx.x; t < NT; t += S, it++) {
        const int sb = it & 1;
        const int p  = t * PT;
        const int b  = p >> 14;
        const int sp = p & (HWP - 1);

        // ---------- Phase 1: warp = group, lane = pixel pair. ----------
        // softmax accumulation f32x2-packed; top-k scalar sort4+merge4 per pixel.
        {
            const int g  = warp;
            const int px = 2 * lane;
            const float* xg  = x + ((size_t)b * CH + g * CG) * HWP + sp + px;
            const ull*  w1p = s_w1p + g * CG;

            ull es2 = 0ull, ys2 = 0ull;              // packed (px0, px1)
            float a0, b0, c0, d0, a1, b1, c1, d1;    // per-pixel sorted top-4

            #pragma unroll
            for (int bt = 0; bt < 8; bt++) {
                const float* xc = xg + (size_t)(4 * bt) * HWP;
                float2 f0 = *(const float2*)(xc + 0 * (size_t)HWP);
                float2 f1 = *(const float2*)(xc + 1 * (size_t)HWP);
                float2 f2 = *(const float2*)(xc + 2 * (size_t)HWP);
                float2 f3 = *(const float2*)(xc + 3 * (size_t)HWP);

                ull v0 = pack2(f0.x, f0.y), v1 = pack2(f1.x, f1.y);
                ull v2 = pack2(f2.x, f2.y), v3 = pack2(f3.x, f3.y);

                ull e0 = pack2(__expf(f0.x), __expf(f0.y));
                ull e1 = pack2(__expf(f1.x), __expf(f1.y));
                ull e2 = pack2(__expf(f2.x), __expf(f2.y));
                ull e3 = pack2(__expf(f3.x), __expf(f3.y));

                es2 = add2(es2, add2(add2(e0, e1), add2(e2, e3)));

                ulonglong2 wA = *(const ulonglong2*)(w1p + 4 * bt);
                ulonglong2 wB = *(const ulonglong2*)(w1p + 4 * bt + 2);
                fma2(ys2, mul2(v0, e0), wA.x);
                fma2(ys2, mul2(v1, e1), wA.y);
                fma2(ys2, mul2(v2, e2), wB.x);
                fma2(ys2, mul2(v3, e3), wB.y);

                if (bt == 0) {
                    sort4(f0.x, f1.x, f2.x, f3.x, a0, b0, c0, d0);
                    sort4(f0.y, f1.y, f2.y, f3.y, a1, b1, c1, d1);
                } else {
                    float sa, sbv, sc, sd;
                    sort4(f0.x, f1.x, f2.x, f3.x, sa, sbv, sc, sd);
                    merge4(a0, b0, c0, d0, sa, sbv, sc, sd);
                    sort4(f0.y, f1.y, f2.y, f3.y, sa, sbv, sc, sd);
                    merge4(a1, b1, c1, d1, sa, sbv, sc, sd);
                }
            }

            float k0 = s_tw1[g * 4 + 0], k1 = s_tw1[g * 4 + 1];
            float k2 = s_tw1[g * 4 + 2], k3 = s_tw1[g * 4 + 3];

            float ysl, ysh, esl, esh;
            unpack2(ys2, ysl, ysh);
            unpack2(es2, esl, esh);

            ulonglong2 st2;
            st2.x = pack2(__fdividef(ysl, esl),
                          fmaf(a0, k0, fmaf(b0, k1, fmaf(c0, k2, d0 * k3))));
            st2.y = pack2(__fdividef(ysh, esh),
                          fmaf(a1, k0, fmaf(b1, k1, fmaf(c1, k2, d1 * k3))));
            *(ulonglong2*)&s_st[sb][g][px] = st2;   // STS.128, conflict-free
        }
        __syncthreads();   // stats(t) ready; the ONLY barrier per tile

        // ---------- Phase 2: warp -> 32 channels; lane -> pixel pair ----------
        {
            const int px0 = 2 * lane;
            ull st0[8], st1[8];
            #pragma unroll
            for (int g2 = 0; g2 < 8; g2++) {
                ulonglong2 v = *(const ulonglong2*)&s_st[sb][g2][px0];  // LDS.128
                st0[g2] = v.x;
                st1[g2] = v.y;
            }
            const float* xb = x   + (size_t)b * CH * HWP + sp;
            float*       ob = out + (size_t)b * CH * HWP + sp;
            const int cb = warp * 32;
            #pragma unroll 4
            for (int ii = 0; ii < 32; ii++) {
                int o = cb + ii;
                float2 xv = *(const float2*)(xb + (size_t)o * HWP + px0);  // L1/L2 hit
                ull acc0 = pack2(xv.x, 0.f);
                ull acc1 = pack2(xv.y, 0.f);
                const ulonglong2* wo = (const ulonglong2*)(s_w2 + o * 8);
                #pragma unroll
                for (int gg = 0; gg < 4; gg++) {
                    ulonglong2 wv = wo[gg];
                    fma2(acc0, st0[2 * gg],     wv.x);
                    fma2(acc1, st1[2 * gg],     wv.x);
                    fma2(acc0, st0[2 * gg + 1], wv.y);
                    fma2(acc1, st1[2 * gg + 1], wv.y);
                }
                float lo0, hi0, lo1, hi1;
                unpack2(acc0, lo0, hi0);
                unpack2(acc1, lo1, hi1);
                __stcs((float2*)(ob + (size_t)o * HWP + px0),
                       make_float2(lo0 + hi0, lo1 + hi1));
            }
        }
        // no trailing barrier: stats double-buffered; buffer sb reused at t+2,
        // ordered behind the next iteration's __syncthreads.
    }
}

extern "C" void kernel_launch(void* const* d_in, const int* in_sizes, int n_in,
                              void* d_out, int out_size) {
    const float* x   = (const float*)d_in[0];
    const float* sw1 = (const float*)d_in[1];
    const float* sw2 = (const float*)d_in[2];
    const float* tw1 = (const float*)d_in[3];
    const float* tw2 = (const float*)d_in[4];
    const float* r   = (const float*)d_in[5];
    float* out = (float*)d_out;

    static int sms = 0;
    if (sms == 0) cudaDeviceGetAttribute(&sms, cudaDevAttrMultiProcessorCount, 0);

    cgblock_kernel<<<3 * sms, TPB>>>(x, sw1, sw2, tw1, tw2, r, out);
}